// round 1
// baseline (speedup 1.0000x reference)
#include <cuda_runtime.h>
#include <cstdint>
#include <math.h>

#define DI __device__ __forceinline__

constexpr int SEQ = 2048;
constexpr int DM  = 1024;
constexpr int NH  = 16;
constexpr int DK  = 64;
constexpr int RAD = 128;          // masksize // 2
constexpr int NBATCH = 2;
constexpr int NROW = NBATCH * SEQ;   // 4096 rows for all projections

// ---------------- scratch (no allocation allowed) ----------------
__device__ __align__(256) float g_q[NBATCH * NH * SEQ * DK];
__device__ __align__(256) float g_k[NBATCH * NH * SEQ * DK];
__device__ __align__(256) float g_v[NBATCH * NH * SEQ * DK];
__device__ __align__(256) float g_x[NBATCH * SEQ * DM];

// ---------------- tf32 helpers ----------------
DI uint32_t f2tf32(float x) {
    uint32_t r;
    asm("cvt.rna.tf32.f32 %0, %1;" : "=r"(r) : "f"(x));
    return r;
}

DI void mma8(float* d, const uint32_t* a, const uint32_t* b) {
    asm volatile(
        "mma.sync.aligned.m16n8k8.row.col.f32.tf32.tf32.f32 "
        "{%0,%1,%2,%3}, {%4,%5,%6,%7}, {%8,%9}, {%0,%1,%2,%3};\n"
        : "+f"(d[0]), "+f"(d[1]), "+f"(d[2]), "+f"(d[3])
        : "r"(a[0]), "r"(a[1]), "r"(a[2]), "r"(a[3]),
          "r"(b[0]), "r"(b[1]));
}

// ======================================================================
// GEMM: out = X[4096,1024] @ W[1024,1024] + bias
// mode 0: out[r*1024 + c]  (plain [B,S,D])
// mode 1: head-scatter to [B,H,S,dk]: b=r>>11, s=r&2047, h=c>>6, d=c&63
// BM=128, BN=128, BK=32, 256 threads (8 warps as 2x4), warp tile 64x32
// ======================================================================
__global__ __launch_bounds__(256)
void gemm_tf32(const float* __restrict__ X, const float* __restrict__ Wt,
               const float* __restrict__ bias, float* __restrict__ out, int mode) {
    __shared__ float As[128 * 36];   // row stride 36 (mod 32 == 4 -> conflict-free A frags)
    __shared__ float Bs[32 * 136];   // row stride 136 (mod 32 == 8 -> conflict-free B frags)

    const int tid  = threadIdx.x;
    const int lane = tid & 31;
    const int warp = tid >> 5;
    const int row0 = blockIdx.y * 128;
    const int col0 = blockIdx.x * 128;
    const int wm = (warp >> 2) * 64;   // 0 or 64
    const int wn = (warp & 3) * 32;    // 0..96

    float acc[4][4][4];
#pragma unroll
    for (int i = 0; i < 4; i++)
#pragma unroll
        for (int j = 0; j < 4; j++)
#pragma unroll
            for (int e = 0; e < 4; e++) acc[i][j][e] = 0.f;

    const int ar = tid >> 3,  ac = (tid & 7) << 2;    // A: 32 rows/pass x 32 cols
    const int br = tid >> 5,  bc = (tid & 31) << 2;   // B: 8 rows/pass x 128 cols

    for (int kt = 0; kt < DM; kt += 32) {
#pragma unroll
        for (int i = 0; i < 4; i++) {
            *(float4*)&As[(ar + 32 * i) * 36 + ac] =
                *(const float4*)&X[(size_t)(row0 + ar + 32 * i) * DM + kt + ac];
        }
#pragma unroll
        for (int i = 0; i < 4; i++) {
            *(float4*)&Bs[(br + 8 * i) * 136 + bc] =
                *(const float4*)&Wt[(size_t)(kt + br + 8 * i) * DM + col0 + bc];
        }
        __syncthreads();

#pragma unroll
        for (int kk = 0; kk < 32; kk += 8) {
            uint32_t af[4][4], bf[4][2];
#pragma unroll
            for (int mt = 0; mt < 4; mt++) {
                const int r = wm + mt * 16 + (lane >> 2);
                const int c = kk + (lane & 3);
                af[mt][0] = f2tf32(As[r * 36 + c]);
                af[mt][1] = f2tf32(As[(r + 8) * 36 + c]);
                af[mt][2] = f2tf32(As[r * 36 + c + 4]);
                af[mt][3] = f2tf32(As[(r + 8) * 36 + c + 4]);
            }
#pragma unroll
            for (int nt = 0; nt < 4; nt++) {
                const int cB = wn + nt * 8 + (lane >> 2);
                const int rB = kk + (lane & 3);
                bf[nt][0] = f2tf32(Bs[rB * 136 + cB]);
                bf[nt][1] = f2tf32(Bs[(rB + 4) * 136 + cB]);
            }
#pragma unroll
            for (int mt = 0; mt < 4; mt++)
#pragma unroll
                for (int nt = 0; nt < 4; nt++) mma8(acc[mt][nt], af[mt], bf[nt]);
        }
        __syncthreads();
    }

    // epilogue
#pragma unroll
    for (int mt = 0; mt < 4; mt++)
#pragma unroll
        for (int nt = 0; nt < 4; nt++) {
            const int r0 = row0 + wm + mt * 16 + (lane >> 2);
            const int c0 = col0 + wn + nt * 8 + ((lane & 3) << 1);
#pragma unroll
            for (int e = 0; e < 4; e++) {
                const int r = r0 + ((e >> 1) << 3);
                const int c = c0 + (e & 1);
                const float v = acc[mt][nt][e] + bias[c];
                if (mode == 0) {
                    out[(size_t)r * DM + c] = v;
                } else {
                    const int b = r >> 11, s2 = r & (SEQ - 1);
                    const int h = c >> 6,  d = c & 63;
                    out[((((size_t)b * NH + h) * SEQ + s2) << 6) + d] = v;
                }
            }
        }
}

// ======================================================================
// Banded attention: one CTA = 64 queries x one (b,h).
// Key window [klo, khi), width <= 320, streamed in 128-key chunks.
// Writes full p_attn rows (zeros outside band) and X = P@V in [B,S,D].
// ======================================================================
constexpr int SQ_STR  = 68;    // mod 32 == 4 -> conflict-free A frags
constexpr int SKV_STR = 76;    // mod 32 == 12 -> conflict-free QK^T B frags, 2-way on PV
constexpr int SS_STR  = 388;   // holds up to 3*128 score cols; mod 32 == 4
constexpr int SMEM_ATT = (64 * SQ_STR + 128 * SKV_STR + 64 * SS_STR) * 4;

__global__ __launch_bounds__(256)
void attn_kernel(float* __restrict__ p_out) {
    extern __shared__ float sm[];
    float* sQ  = sm;
    float* sKV = sm + 64 * SQ_STR;
    float* sS  = sKV + 128 * SKV_STR;

    const int tid  = threadIdx.x;
    const int lane = tid & 31;
    const int warp = tid >> 5;
    const int bh = blockIdx.y;
    const int q0 = blockIdx.x * 64;
    const int klo = max(0, q0 - RAD);
    const int khi = min(SEQ, q0 + 64 + RAD);
    const int Wd  = khi - klo;
    const int nch = (Wd + 127) >> 7;

    const float* Qg = g_q + ((size_t)bh * SEQ + q0) * DK;
    const float* Kg = g_k + (size_t)bh * SEQ * DK;
    const float* Vg = g_v + (size_t)bh * SEQ * DK;

    // load Q (64 x 64)
    {
        const int r = tid >> 4, c = (tid & 15) << 2;
#pragma unroll
        for (int i = 0; i < 4; i++)
            *(float4*)&sQ[(r + 16 * i) * SQ_STR + c] =
                *(const float4*)&Qg[(size_t)(r + 16 * i) * DK + c];
    }

    const int wm  = (warp >> 2) * 32;  // 0 or 32
    const int wn4 = warp & 3;

    // ---- scores: S = (Q @ K^T) * (1/8) into sS ----
    for (int ci = 0; ci < nch; ci++) {
        const int ck0 = klo + (ci << 7);
        const int cw  = min(128, khi - ck0);
        __syncthreads();   // prior consumers of sKV done; also orders sQ stores (iter 0)
        {
            const int r = tid >> 4, c = (tid & 15) << 2;
#pragma unroll
            for (int i = 0; i < 8; i++) {
                const int rr = r + (i << 4);
                float4 v = make_float4(0.f, 0.f, 0.f, 0.f);
                if (rr < cw) v = *(const float4*)&Kg[(size_t)(ck0 + rr) * DK + c];
                *(float4*)&sKV[rr * SKV_STR + c] = v;
            }
        }
        __syncthreads();

        float sacc[2][4][4];
#pragma unroll
        for (int i = 0; i < 2; i++)
#pragma unroll
            for (int j = 0; j < 4; j++)
#pragma unroll
                for (int e = 0; e < 4; e++) sacc[i][j][e] = 0.f;

#pragma unroll
        for (int kk = 0; kk < 64; kk += 8) {
            uint32_t af[2][4], bf[4][2];
#pragma unroll
            for (int mt = 0; mt < 2; mt++) {
                const int r = wm + mt * 16 + (lane >> 2);
                const int c = kk + (lane & 3);
                af[mt][0] = f2tf32(sQ[r * SQ_STR + c]);
                af[mt][1] = f2tf32(sQ[(r + 8) * SQ_STR + c]);
                af[mt][2] = f2tf32(sQ[r * SQ_STR + c + 4]);
                af[mt][3] = f2tf32(sQ[(r + 8) * SQ_STR + c + 4]);
            }
#pragma unroll
            for (int nt = 0; nt < 4; nt++) {
                const int key = wn4 * 32 + nt * 8 + (lane >> 2);
                const int kd  = kk + (lane & 3);
                bf[nt][0] = f2tf32(sKV[key * SKV_STR + kd]);
                bf[nt][1] = f2tf32(sKV[key * SKV_STR + kd + 4]);
            }
#pragma unroll
            for (int mt = 0; mt < 2; mt++)
#pragma unroll
                for (int nt = 0; nt < 4; nt++) mma8(sacc[mt][nt], af[mt], bf[nt]);
        }
#pragma unroll
        for (int mt = 0; mt < 2; mt++)
#pragma unroll
            for (int nt = 0; nt < 4; nt++) {
#pragma unroll
                for (int e = 0; e < 4; e++) {
                    const int r = wm + mt * 16 + (lane >> 2) + ((e >> 1) << 3);
                    const int c = (ci << 7) + wn4 * 32 + nt * 8 + ((lane & 3) << 1) + (e & 1);
                    sS[r * SS_STR + c] = sacc[mt][nt][e] * 0.125f;
                }
            }
    }
    __syncthreads();

    // ---- softmax over the band, zero out-of-band inside window ----
    for (int rr = 0; rr < 8; rr++) {
        const int row = warp * 8 + rr;
        const int qi  = q0 + row;
        const int c0  = max(0, qi - RAD) - klo;
        const int c1  = min(SEQ - 1, qi + RAD) - klo;   // inclusive
        float mx = -1e30f;
        for (int c = c0 + lane; c <= c1; c += 32) mx = fmaxf(mx, sS[row * SS_STR + c]);
#pragma unroll
        for (int o = 16; o; o >>= 1) mx = fmaxf(mx, __shfl_xor_sync(0xffffffffu, mx, o));
        float sum = 0.f;
        for (int c = c0 + lane; c <= c1; c += 32) {
            const float e = expf(sS[row * SS_STR + c] - mx);
            sS[row * SS_STR + c] = e;
            sum += e;
        }
#pragma unroll
        for (int o = 16; o; o >>= 1) sum += __shfl_xor_sync(0xffffffffu, sum, o);
        const float inv = 1.f / sum;
        for (int c = c0 + lane; c <= c1; c += 32) sS[row * SS_STR + c] *= inv;
        for (int c = lane; c < c0; c += 32) sS[row * SS_STR + c] = 0.f;
        for (int c = c1 + 1 + lane; c < Wd; c += 32) sS[row * SS_STR + c] = 0.f;
    }
    __syncthreads();

    // ---- write p_attn: full 2048-wide rows, zeros outside [klo, khi) ----
    {
        float* Pg = p_out + ((size_t)bh * SEQ + q0) * SEQ;
        for (int idx = tid; idx < 64 * (SEQ / 4); idx += 256) {
            const int row = idx >> 9;
            const int j   = (idx & 511) << 2;
            float4 v;
            if (j >= klo && j < khi) v = *(float4*)&sS[row * SS_STR + (j - klo)];
            else                     v = make_float4(0.f, 0.f, 0.f, 0.f);
            *(float4*)&Pg[(size_t)row * SEQ + j] = v;
        }
    }

    // ---- O = P @ V (64 x 64), V streamed in chunks into sKV ----
    float oacc[2][2][4];
#pragma unroll
    for (int i = 0; i < 2; i++)
#pragma unroll
        for (int j = 0; j < 2; j++)
#pragma unroll
            for (int e = 0; e < 4; e++) oacc[i][j][e] = 0.f;

    for (int ci = 0; ci < nch; ci++) {
        const int ck0 = klo + (ci << 7);
        const int cw  = min(128, khi - ck0);
        __syncthreads();
        {
            const int r = tid >> 4, c = (tid & 15) << 2;
#pragma unroll
            for (int i = 0; i < 8; i++) {
                const int rr = r + (i << 4);
                float4 v = make_float4(0.f, 0.f, 0.f, 0.f);
                if (rr < cw) v = *(const float4*)&Vg[(size_t)(ck0 + rr) * DK + c];
                *(float4*)&sKV[rr * SKV_STR + c] = v;
            }
        }
        __syncthreads();

#pragma unroll
        for (int kk = 0; kk < 128; kk += 8) {
            uint32_t af[2][4], bf[2][2];
#pragma unroll
            for (int mt = 0; mt < 2; mt++) {
                const int r = wm + mt * 16 + (lane >> 2);
                const int c = (ci << 7) + kk + (lane & 3);
                af[mt][0] = f2tf32(sS[r * SS_STR + c]);
                af[mt][1] = f2tf32(sS[(r + 8) * SS_STR + c]);
                af[mt][2] = f2tf32(sS[r * SS_STR + c + 4]);
                af[mt][3] = f2tf32(sS[(r + 8) * SS_STR + c + 4]);
            }
#pragma unroll
            for (int nt = 0; nt < 2; nt++) {
                const int n  = wn4 * 16 + nt * 8 + (lane >> 2);
                const int kd = kk + (lane & 3);
                bf[nt][0] = f2tf32(sKV[kd * SKV_STR + n]);
                bf[nt][1] = f2tf32(sKV[(kd + 4) * SKV_STR + n]);
            }
#pragma unroll
            for (int mt = 0; mt < 2; mt++)
#pragma unroll
                for (int nt = 0; nt < 2; nt++) mma8(oacc[mt][nt], af[mt], bf[nt]);
        }
    }

    // ---- write X in [B,S,D] (head-concat) layout ----
    {
        const int b = bh >> 4, h = bh & 15;
#pragma unroll
        for (int mt = 0; mt < 2; mt++)
#pragma unroll
            for (int nt = 0; nt < 2; nt++) {
#pragma unroll
                for (int e = 0; e < 4; e++) {
                    const int r = wm + mt * 16 + (lane >> 2) + ((e >> 1) << 3);
                    const int c = wn4 * 16 + nt * 8 + ((lane & 3) << 1) + (e & 1);
                    g_x[((size_t)b * SEQ + q0 + r) * DM + (h << 6) + c] = oacc[mt][nt][e];
                }
            }
    }
}

// ======================================================================
// Launch
// inputs: 0 query, 1 key, 2 value, 3 Wq, 4 bq, 5 Wk, 6 bk, 7 Wv, 8 bv,
//         9 Wo, 10 bo
// output: concat(out[2,2048,1024], p_attn[2,16,2048,2048]) fp32
// ======================================================================
extern "C" void kernel_launch(void* const* d_in, const int* in_sizes, int n_in,
                              void* d_out, int out_size) {
    const float* query = (const float*)d_in[0];
    const float* key_  = (const float*)d_in[1];
    const float* value = (const float*)d_in[2];
    const float* Wq = (const float*)d_in[3];
    const float* bq = (const float*)d_in[4];
    const float* Wk = (const float*)d_in[5];
    const float* bk = (const float*)d_in[6];
    const float* Wv = (const float*)d_in[7];
    const float* bv = (const float*)d_in[8];
    const float* Wo = (const float*)d_in[9];
    const float* bo = (const float*)d_in[10];

    float* out = (float*)d_out;
    float* p   = out + (size_t)NBATCH * SEQ * DM;

    float *qp, *kp, *vp, *xp;
    cudaGetSymbolAddress((void**)&qp, g_q);
    cudaGetSymbolAddress((void**)&kp, g_k);
    cudaGetSymbolAddress((void**)&vp, g_v);
    cudaGetSymbolAddress((void**)&xp, g_x);

    // Idempotent; already applied on the pre-capture correctness call.
    cudaFuncSetAttribute((const void*)attn_kernel,
                         cudaFuncAttributeMaxDynamicSharedMemorySize, SMEM_ATT);

    const dim3 gg(DM / 128, NROW / 128);   // (8, 32)
    gemm_tf32<<<gg, 256>>>(query, Wq, bq, qp, 1);
    gemm_tf32<<<gg, 256>>>(key_,  Wk, bk, kp, 1);
    gemm_tf32<<<gg, 256>>>(value, Wv, bv, vp, 1);

    attn_kernel<<<dim3(SEQ / 64, NBATCH * NH), 256, SMEM_ATT>>>(p);

    gemm_tf32<<<gg, 256>>>(xp, Wo, bo, out, 0);
}